// round 11
// baseline (speedup 1.0000x reference)
#include <cuda_runtime.h>
#include <cuda_fp16.h>
#include <cstdint>
#include <math.h>

// Problem constants
#define PB 8
#define PS 2048
#define PD 1024
#define PC 4096

#define BM 128
#define BN 128

// ===========================================================================
// helpers
// ===========================================================================
__device__ __forceinline__ uint32_t smem_u32(const void* p) {
    uint32_t a;
    asm("{ .reg .u64 t; cvta.to.shared.u64 t, %1; cvt.u32.u64 %0, t; }"
        : "=r"(a) : "l"(p));
    return a;
}

__device__ __forceinline__ void cp16(uint32_t dst, const void* src) {
    asm volatile("cp.async.cg.shared.global [%0], [%1], 16;\n" :: "r"(dst), "l"(src));
}

#define CP_COMMIT() asm volatile("cp.async.commit_group;\n" ::: "memory")

template<int N>
__device__ __forceinline__ void cp_wait() {
    asm volatile("cp.async.wait_group %0;\n" :: "n"(N) : "memory");
}

#define LDMX4(r0, r1, r2, r3, addr) \
    asm volatile("ldmatrix.sync.aligned.m8n8.x4.shared.b16 {%0,%1,%2,%3}, [%4];" \
        : "=r"(r0), "=r"(r1), "=r"(r2), "=r"(r3) : "r"(addr))

#define MMA16816(d, a, b0, b1) \
    asm volatile("mma.sync.aligned.m16n8k16.row.col.f32.f16.f16.f32 " \
        "{%0,%1,%2,%3}, {%4,%5,%6,%7}, {%8,%9}, {%0,%1,%2,%3};" \
        : "+f"((d)[0]), "+f"((d)[1]), "+f"((d)[2]), "+f"((d)[3]) \
        : "r"((a)[0]), "r"((a)[1]), "r"((a)[2]), "r"((a)[3]), "r"(b0), "r"(b1))

// ===========================================================================
// Scratch (__device__ globals — no runtime allocation)
// ===========================================================================
__device__ __half g_Xh [(size_t)PB * PS * PD];   // X split hi      [B*S, D]
__device__ __half g_Xl [(size_t)PB * PS * PD];   // X split lo
__device__ __half g_Lh [(size_t)PC * PD];        // label split hi  [C, D]
__device__ __half g_Ll [(size_t)PC * PD];
__device__ __half g_XhT[(size_t)PB * PD * PS];   // X^T hi          [B][D, S]
__device__ __half g_AhT[(size_t)PB * PC * PS];   // A^T hi          [B][C, S]
__device__ float2 g_part [(size_t)PB * PS * 64]; // per-(row, 64col-tile) (max, sumexp)
__device__ float2 g_stats[(size_t)PB * PS];      // per-row (max, 1/sum)

// ===========================================================================
// fp32 -> fp16 hi/lo split (lo unscaled; |lo| <= 2^-12|x|)
// ===========================================================================
__global__ void split_kernel(const float* __restrict__ in, __half* __restrict__ ho,
                             __half* __restrict__ lo, int n4) {
    int i = blockIdx.x * blockDim.x + threadIdx.x;
    if (i >= n4) return;
    float4 v = ((const float4*)in)[i];
    __half h0 = __float2half_rn(v.x), h1 = __float2half_rn(v.y);
    __half h2 = __float2half_rn(v.z), h3 = __float2half_rn(v.w);
    __half l0 = __float2half_rn(v.x - __half2float(h0));
    __half l1 = __float2half_rn(v.y - __half2float(h1));
    __half l2 = __float2half_rn(v.z - __half2float(h2));
    __half l3 = __float2half_rn(v.w - __half2float(h3));
    ((__half2*)ho)[2 * i]     = __halves2half2(h0, h1);
    ((__half2*)ho)[2 * i + 1] = __halves2half2(h2, h3);
    ((__half2*)lo)[2 * i]     = __halves2half2(l0, l1);
    ((__half2*)lo)[2 * i + 1] = __halves2half2(l2, l3);
}

// ===========================================================================
// Transposing fp32 -> fp16 (hi only): src [srcRows, srcCols] -> dst [srcCols, srcRows]
// ===========================================================================
__global__ __launch_bounds__(256)
void transpose_h(const float* __restrict__ src, __half* __restrict__ hT,
                 int srcRows, int srcCols, size_t srcBatch, size_t dstBatch) {
    __shared__ float tile[32][65];
    int b = blockIdx.z;
    src += (size_t)b * srcBatch;
    hT  += (size_t)b * dstBatch;
    int c0 = blockIdx.x * 32;
    int r0 = blockIdx.y * 64;
    int t = threadIdx.x;
    int lc = t & 31, lr = t >> 5;
    #pragma unroll
    for (int j = 0; j < 8; ++j)
        tile[lc][lr + 8 * j] = src[(size_t)(r0 + lr + 8 * j) * srcCols + c0 + lc];
    __syncthreads();
    int oc = t >> 3, rp = t & 7;
    #pragma unroll
    for (int j = 0; j < 4; ++j) {
        int rr = (rp + 8 * j) * 2;
        __half h0 = __float2half_rn(tile[oc][rr]);
        __half h1 = __float2half_rn(tile[oc][rr + 1]);
        size_t o = (size_t)(c0 + oc) * srcRows + r0 + rr;
        *(__half2*)(hT + o) = __halves2half2(h0, h1);
    }
}

// ===========================================================================
// HMMA GEMM, templated:
//   NT=3: Out = (Ah+Al)*(Bh+Bl)^T  via  ah*bh + ah*bl + al*bh  (split-fp16)
//   NT=1: Out = Ah*Bh^T                                         (pure fp16)
//   STATS: epilogue also writes per-(row, 64-col warp tile) softmax partials
// A: [M,K] K-major halves, B: [N,K] K-major halves, Out fp32 [M,N].
// CTA 128x128, 8 warps (32x64), BKH k-halves/stage, STAGES-deep cp.async
// pipeline with wait_group(STAGES-2); one __syncthreads per iter.
// ===========================================================================
template<int NT, int BKH, int STAGES, bool STATS>
__global__ __launch_bounds__(256, 2)
void gemm_hmma(const __half* __restrict__ Ah, const __half* __restrict__ Al,
               const __half* __restrict__ Bh, const __half* __restrict__ Bl,
               float* __restrict__ Out,
               int lda, int ldb, int ldc, int K,
               size_t aBatch, size_t bBatch, size_t cBatch) {
    constexpr int PIT   = BKH + 8;            // halves per smem row (conflict-free)
    constexpr int TILEB = 128 * PIT * 2;      // bytes per operand tile
    constexpr int NOP   = (NT == 3) ? 4 : 2;  // tiles per stage
    constexpr int STB   = NOP * TILEB;        // stage bytes
    constexpr int CPR   = BKH / 8;            // 16B chunks per row
    constexpr int RST   = 256 / CPR;          // rows per loader pass

    extern __shared__ char smem[];
    const uint32_t sb = smem_u32(smem);
    const int tid = threadIdx.x;
    const int lane = tid & 31;
    const int wid = tid >> 5;

    const int b = blockIdx.z;
    Ah += (size_t)b * aBatch;
    Bh += (size_t)b * bBatch;
    Out += (size_t)b * cBatch;
    if (NT == 3) { Al += (size_t)b * aBatch; Bl += (size_t)b * bBatch; }

    const int bm = blockIdx.y * BM;
    const int bn = blockIdx.x * BN;

    // loader mapping
    const int r0 = tid / CPR;
    const int cb = (tid % CPR) * 16;               // byte col in smem row
    const int chalves = (tid % CPR) * 8;           // k-offset (halves)
    const uint32_t sOffBase = (uint32_t)r0 * (PIT * 2) + cb;

    const __half* pAh = Ah + (size_t)(bm + r0) * lda + chalves;
    const __half* pBh = Bh + (size_t)(bn + r0) * ldb + chalves;
    const __half* pAl = (NT == 3) ? Al + (size_t)(bm + r0) * lda + chalves : pAh;
    const __half* pBl = (NT == 3) ? Bl + (size_t)(bn + r0) * ldb + chalves : pBh;

    const int warpM = (wid & 3) * 32;
    const int warpN = (wid >> 2) * 64;

    float acc[2][8][4];
    #pragma unroll
    for (int i = 0; i < 2; i++)
        #pragma unroll
        for (int j = 0; j < 8; j++)
            #pragma unroll
            for (int k = 0; k < 4; k++) acc[i][j][k] = 0.0f;

    const int nIter = K / BKH;

    #define ISSUE_STAGE(st, ko) do {                                             \
        _Pragma("unroll")                                                        \
        for (int rr = 0; rr < 128; rr += RST) {                                  \
            const uint32_t so = sOffBase + (uint32_t)rr * (PIT * 2);             \
            cp16((st) + 0 * TILEB + so, pAh + (size_t)rr * lda + (ko));          \
            if (NT == 3) cp16((st) + 2 * TILEB + so, pAl + (size_t)rr * lda + (ko)); \
            cp16((st) + 1 * TILEB + so, pBh + (size_t)rr * ldb + (ko));          \
            if (NT == 3) cp16((st) + 3 * TILEB + so, pBl + (size_t)rr * ldb + (ko)); \
        }                                                                        \
        CP_COMMIT();                                                             \
    } while (0)

    // prologue: stages 0..STAGES-2
    #pragma unroll
    for (int i = 0; i < STAGES - 1; ++i)
        ISSUE_STAGE(sb + i * STB, (size_t)i * BKH);

    const uint32_t lrow = (uint32_t)(lane & 15) * (PIT * 2) + (lane & 16);

    int cbuf = 0;                       // buffer of stage t
    int ibuf = (STAGES - 1) % STAGES;   // buffer to fill next

    for (int t = 0; t < nIter; ++t) {
        cp_wait<STAGES - 2>();  // stage t resident (requested STAGES-1 iters ago)
        __syncthreads();        // compute(t-1) done -> its buffer reusable

        if (t + STAGES - 1 < nIter) {
            ISSUE_STAGE(sb + ibuf * STB, (size_t)(t + STAGES - 1) * BKH);
        }
        ibuf = (ibuf + 1 == STAGES) ? 0 : ibuf + 1;

        const uint32_t s0 = sb + cbuf * STB;
        cbuf = (cbuf + 1 == STAGES) ? 0 : cbuf + 1;

        #pragma unroll
        for (int kk = 0; kk < BKH / 16; ++kk) {
            uint32_t ah[2][4], al[2][4];
            #pragma unroll
            for (int mt = 0; mt < 2; ++mt) {
                const uint32_t aaddr = s0 + (uint32_t)(warpM + mt * 16) * (PIT * 2)
                                       + lrow + kk * 32;
                LDMX4(ah[mt][0], ah[mt][1], ah[mt][2], ah[mt][3], aaddr);
                if (NT == 3)
                    LDMX4(al[mt][0], al[mt][1], al[mt][2], al[mt][3], aaddr + 2 * TILEB);
            }
            #pragma unroll
            for (int g = 0; g < 4; ++g) {
                const uint32_t baddr = s0 + (uint32_t)(warpN + g * 16) * (PIT * 2)
                                       + lrow + kk * 32;
                uint32_t bh0, bh1, bh2, bh3;
                LDMX4(bh0, bh1, bh2, bh3, baddr + 1 * TILEB);
                if (NT == 3) {
                    uint32_t bl0, bl1, bl2, bl3;
                    LDMX4(bl0, bl1, bl2, bl3, baddr + 3 * TILEB);
                    // interleave: 4 independent chains, dependent MMAs >=4 apart
                    #pragma unroll
                    for (int mt = 0; mt < 2; ++mt) {
                        MMA16816(acc[mt][2 * g],     ah[mt], bh0, bh2);
                        MMA16816(acc[mt][2 * g + 1], ah[mt], bh1, bh3);
                    }
                    #pragma unroll
                    for (int mt = 0; mt < 2; ++mt) {
                        MMA16816(acc[mt][2 * g],     ah[mt], bl0, bl2);
                        MMA16816(acc[mt][2 * g + 1], ah[mt], bl1, bl3);
                    }
                    #pragma unroll
                    for (int mt = 0; mt < 2; ++mt) {
                        MMA16816(acc[mt][2 * g],     al[mt], bh0, bh2);
                        MMA16816(acc[mt][2 * g + 1], al[mt], bh1, bh3);
                    }
                } else {
                    #pragma unroll
                    for (int mt = 0; mt < 2; ++mt) {
                        MMA16816(acc[mt][2 * g],     ah[mt], bh0, bh2);
                        MMA16816(acc[mt][2 * g + 1], ah[mt], bh1, bh3);
                    }
                }
            }
        }
    }
    #undef ISSUE_STAGE

    // ---- softmax partials: per-(row, 64-col warp tile) (max, sumexp) ----
    if (STATS) {
        #pragma unroll
        for (int mt = 0; mt < 2; ++mt) {
            float m0 = -3.4e38f, m1 = -3.4e38f;
            #pragma unroll
            for (int nf = 0; nf < 8; ++nf) {
                m0 = fmaxf(m0, fmaxf(acc[mt][nf][0], acc[mt][nf][1]));
                m1 = fmaxf(m1, fmaxf(acc[mt][nf][2], acc[mt][nf][3]));
            }
            m0 = fmaxf(m0, __shfl_xor_sync(0xFFFFFFFFu, m0, 1));
            m0 = fmaxf(m0, __shfl_xor_sync(0xFFFFFFFFu, m0, 2));
            m1 = fmaxf(m1, __shfl_xor_sync(0xFFFFFFFFu, m1, 1));
            m1 = fmaxf(m1, __shfl_xor_sync(0xFFFFFFFFu, m1, 2));
            float s0 = 0.0f, s1 = 0.0f;
            #pragma unroll
            for (int nf = 0; nf < 8; ++nf) {
                s0 += __expf(acc[mt][nf][0] - m0) + __expf(acc[mt][nf][1] - m0);
                s1 += __expf(acc[mt][nf][2] - m1) + __expf(acc[mt][nf][3] - m1);
            }
            s0 += __shfl_xor_sync(0xFFFFFFFFu, s0, 1);
            s0 += __shfl_xor_sync(0xFFFFFFFFu, s0, 2);
            s1 += __shfl_xor_sync(0xFFFFFFFFu, s1, 1);
            s1 += __shfl_xor_sync(0xFFFFFFFFu, s1, 2);
            if ((lane & 3) == 0) {
                const int row0 = bm + warpM + mt * 16 + (lane >> 2);
                const int pcol = (bn >> 6) + (warpN >> 6);
                g_part[(size_t)row0 * 64 + pcol]       = make_float2(m0, s0);
                g_part[(size_t)(row0 + 8) * 64 + pcol] = make_float2(m1, s1);
            }
        }
    }

    // ---- epilogue: direct fp32 stores (quad-contiguous 32B segments) ----
    #pragma unroll
    for (int mt = 0; mt < 2; ++mt) {
        #pragma unroll
        for (int nf = 0; nf < 8; ++nf) {
            const int row = bm + warpM + mt * 16 + (lane >> 2);
            const int col = bn + warpN + nf * 8 + (lane & 3) * 2;
            *(float2*)&Out[(size_t)row * ldc + col] =
                make_float2(acc[mt][nf][0], acc[mt][nf][1]);
            *(float2*)&Out[(size_t)(row + 8) * ldc + col] =
                make_float2(acc[mt][nf][2], acc[mt][nf][3]);
        }
    }
}

// ---------------------------------------------------------------------------
// Merge 64 per-tile partials per row -> per-row (max, 1/sum). One warp/row.
// ---------------------------------------------------------------------------
__global__ __launch_bounds__(256)
void merge_stats() {
    const int row = blockIdx.x * 8 + (threadIdx.x >> 5);
    const int lane = threadIdx.x & 31;
    float2 p0 = g_part[(size_t)row * 64 + lane];
    float2 p1 = g_part[(size_t)row * 64 + 32 + lane];
    float m = fmaxf(p0.x, p1.x);
    #pragma unroll
    for (int o = 16; o > 0; o >>= 1)
        m = fmaxf(m, __shfl_xor_sync(0xFFFFFFFFu, m, o));
    float s = p0.y * __expf(p0.x - m) + p1.y * __expf(p1.x - m);
    #pragma unroll
    for (int o = 16; o > 0; o >>= 1)
        s += __shfl_xor_sync(0xFFFFFFFFu, s, o);
    if (lane == 0) g_stats[row] = make_float2(m, 1.0f / s);
}

// ---------------------------------------------------------------------------
// Normalize scores -> probs (in place, fp32) AND write fp16 transposed A^T.
// Tile 32 cols x 64 rows per block (like transpose_h).
// ---------------------------------------------------------------------------
__global__ __launch_bounds__(256)
void norm_transpose(float* __restrict__ A, __half* __restrict__ AhT) {
    __shared__ float tile[32][65];
    __shared__ float2 st[64];
    const int b = blockIdx.z;
    float* Ab = A + (size_t)b * PS * PC;
    __half* hT = AhT + (size_t)b * PC * PS;
    const int c0 = blockIdx.x * 32;
    const int r0 = blockIdx.y * 64;
    const int t = threadIdx.x;
    if (t < 64) st[t] = g_stats[(size_t)b * PS + r0 + t];
    __syncthreads();
    const int lc = t & 31, lr = t >> 5;
    #pragma unroll
    for (int j = 0; j < 8; ++j) {
        const int row = lr + 8 * j;
        const size_t off = (size_t)(r0 + row) * PC + c0 + lc;
        const float2 s = st[row];
        const float p = __expf(Ab[off] - s.x) * s.y;
        tile[lc][row] = p;
        Ab[off] = p;
    }
    __syncthreads();
    const int oc = t >> 3, rp = t & 7;
    #pragma unroll
    for (int j = 0; j < 4; ++j) {
        const int rr = (rp + 8 * j) * 2;
        __half h0 = __float2half_rn(tile[oc][rr]);
        __half h1 = __float2half_rn(tile[oc][rr + 1]);
        const size_t o = (size_t)(c0 + oc) * PS + r0 + rr;
        *(__half2*)(hT + o) = __halves2half2(h0, h1);
    }
}

// ===========================================================================
// Launch.  d_out layout: [output (B*C*D floats) | A (B*S*C floats)]
// ===========================================================================
extern "C" void kernel_launch(void* const* d_in, const int* in_sizes, int n_in,
                              void* d_out, int out_size) {
    const float* x = (const float*)d_in[0];    // [B,S,D]
    const float* lab = (const float*)d_in[1];  // [C,D]
    float* out = (float*)d_out;
    float* Aout = out + (size_t)PB * PC * PD;  // [B*S, C]

    void *pXh, *pXl, *pLh, *pLl, *pXhT, *pAhT;
    cudaGetSymbolAddress(&pXh, g_Xh);   cudaGetSymbolAddress(&pXl, g_Xl);
    cudaGetSymbolAddress(&pLh, g_Lh);   cudaGetSymbolAddress(&pLl, g_Ll);
    cudaGetSymbolAddress(&pXhT, g_XhT); cudaGetSymbolAddress(&pAhT, g_AhT);

    // GEMM1: NT=3, BK=32, 4 stages -> 4*40960 = 163840 B
    const int SMEM_G1 = 4 * 4 * 128 * 40 * 2;
    // GEMM2: NT=1, BK=64, 3 stages -> 3*36864 = 110592 B
    const int SMEM_G2 = 3 * 2 * 128 * 72 * 2;
    cudaFuncSetAttribute((const void*)gemm_hmma<3, 32, 4, true>,
                         cudaFuncAttributeMaxDynamicSharedMemorySize, SMEM_G1);
    cudaFuncSetAttribute((const void*)gemm_hmma<1, 64, 3, false>,
                         cudaFuncAttributeMaxDynamicSharedMemorySize, SMEM_G2);

    // 1. fp16 splits of X and L
    split_kernel<<<(PB * PS * PD / 4 + 255) / 256, 256>>>(
        x, (__half*)pXh, (__half*)pXl, PB * PS * PD / 4);
    split_kernel<<<(PC * PD / 4 + 255) / 256, 256>>>(
        lab, (__half*)pLh, (__half*)pLl, PC * PD / 4);

    // 2. X^T (hi only) per batch: [S,D] -> [D,S]
    {
        dim3 g(PD / 32, PS / 64, PB);
        transpose_h<<<g, 256>>>(x, (__half*)pXhT, PS, PD,
                                (size_t)PS * PD, (size_t)PD * PS);
    }

    // 3. GEMM1 (split-fp16, 3 terms + softmax partials): scores[B*S, C] = X @ L^T
    {
        dim3 g(PC / BN, (PB * PS) / BM, 1);
        gemm_hmma<3, 32, 4, true><<<g, 256, SMEM_G1>>>(
            (const __half*)pXh, (const __half*)pXl,
            (const __half*)pLh, (const __half*)pLl,
            Aout, PD, PD, PC, PD, 0, 0, 0);
    }

    // 4. merge row partials -> (max, 1/sum)
    merge_stats<<<PB * PS / 8, 256>>>();

    // 5. normalize scores in place + write fp16 A^T
    {
        dim3 g(PC / 32, PS / 64, PB);
        norm_transpose<<<g, 256>>>(Aout, (__half*)pAhT);
    }

    // 6. GEMM2 (pure fp16): out[C, D] = A^T @ X   per batch
    {
        dim3 g(PD / BN, PC / BM, PB);
        gemm_hmma<1, 64, 3, false><<<g, 256, SMEM_G2>>>(
            (const __half*)pAhT, (const __half*)pAhT,
            (const __half*)pXhT, (const __half*)pXhT,
            out, PS, PS, PD, PS,
            (size_t)PC * PS, (size_t)PD * PS, (size_t)PC * PD);
    }
}

// round 13
// speedup vs baseline: 1.2277x; 1.2277x over previous
#include <cuda_runtime.h>
#include <cuda_fp16.h>
#include <cstdint>
#include <math.h>

// Problem constants
#define PB 8
#define PS 2048
#define PD 1024
#define PC 4096

#define BM 128
#define BN 128

// ===========================================================================
// helpers
// ===========================================================================
__device__ __forceinline__ uint32_t smem_u32(const void* p) {
    uint32_t a;
    asm("{ .reg .u64 t; cvta.to.shared.u64 t, %1; cvt.u32.u64 %0, t; }"
        : "=r"(a) : "l"(p));
    return a;
}

__device__ __forceinline__ void cp16(uint32_t dst, const void* src) {
    asm volatile("cp.async.cg.shared.global [%0], [%1], 16;\n" :: "r"(dst), "l"(src));
}

#define CP_COMMIT() asm volatile("cp.async.commit_group;\n" ::: "memory")

template<int N>
__device__ __forceinline__ void cp_wait() {
    asm volatile("cp.async.wait_group %0;\n" :: "n"(N) : "memory");
}

#define LDMX4(r0, r1, r2, r3, addr) \
    asm volatile("ldmatrix.sync.aligned.m8n8.x4.shared.b16 {%0,%1,%2,%3}, [%4];" \
        : "=r"(r0), "=r"(r1), "=r"(r2), "=r"(r3) : "r"(addr))

#define MMA16816(d, a, b0, b1) \
    asm volatile("mma.sync.aligned.m16n8k16.row.col.f32.f16.f16.f32 " \
        "{%0,%1,%2,%3}, {%4,%5,%6,%7}, {%8,%9}, {%0,%1,%2,%3};" \
        : "+f"((d)[0]), "+f"((d)[1]), "+f"((d)[2]), "+f"((d)[3]) \
        : "r"((a)[0]), "r"((a)[1]), "r"((a)[2]), "r"((a)[3]), "r"(b0), "r"(b1))

// ===========================================================================
// Scratch (__device__ globals — no runtime allocation)
// ===========================================================================
__device__ __half g_Xh [(size_t)PB * PS * PD];   // X split hi      [B*S, D]
__device__ __half g_Xl [(size_t)PB * PS * PD];   // X split lo
__device__ __half g_Lh [(size_t)PC * PD];        // label split hi  [C, D]
__device__ __half g_Ll [(size_t)PC * PD];
__device__ __half g_XhT[(size_t)PB * PD * PS];   // X^T hi          [B][D, S]
__device__ __half g_AhT[(size_t)PB * PC * PS];   // A^T hi          [B][C, S]
__device__ float2 g_part [(size_t)PB * PS * 64]; // per-(row, 64col-tile) (max, sumexp)
__device__ float2 g_stats[(size_t)PB * PS];      // per-row (max, 1/sum)

// ===========================================================================
// fp32 -> fp16 hi/lo split (lo unscaled; |lo| <= 2^-12|x|)
// ===========================================================================
__global__ void split_kernel(const float* __restrict__ in, __half* __restrict__ ho,
                             __half* __restrict__ lo, int n4) {
    int i = blockIdx.x * blockDim.x + threadIdx.x;
    if (i >= n4) return;
    float4 v = ((const float4*)in)[i];
    __half h0 = __float2half_rn(v.x), h1 = __float2half_rn(v.y);
    __half h2 = __float2half_rn(v.z), h3 = __float2half_rn(v.w);
    __half l0 = __float2half_rn(v.x - __half2float(h0));
    __half l1 = __float2half_rn(v.y - __half2float(h1));
    __half l2 = __float2half_rn(v.z - __half2float(h2));
    __half l3 = __float2half_rn(v.w - __half2float(h3));
    ((__half2*)ho)[2 * i]     = __halves2half2(h0, h1);
    ((__half2*)ho)[2 * i + 1] = __halves2half2(h2, h3);
    ((__half2*)lo)[2 * i]     = __halves2half2(l0, l1);
    ((__half2*)lo)[2 * i + 1] = __halves2half2(l2, l3);
}

// ===========================================================================
// Transposing fp32 -> fp16 (hi only): src [srcRows, srcCols] -> dst [srcCols, srcRows]
// ===========================================================================
__global__ __launch_bounds__(256)
void transpose_h(const float* __restrict__ src, __half* __restrict__ hT,
                 int srcRows, int srcCols, size_t srcBatch, size_t dstBatch) {
    __shared__ float tile[32][65];
    int b = blockIdx.z;
    src += (size_t)b * srcBatch;
    hT  += (size_t)b * dstBatch;
    int c0 = blockIdx.x * 32;
    int r0 = blockIdx.y * 64;
    int t = threadIdx.x;
    int lc = t & 31, lr = t >> 5;
    #pragma unroll
    for (int j = 0; j < 8; ++j)
        tile[lc][lr + 8 * j] = src[(size_t)(r0 + lr + 8 * j) * srcCols + c0 + lc];
    __syncthreads();
    int oc = t >> 3, rp = t & 7;
    #pragma unroll
    for (int j = 0; j < 4; ++j) {
        int rr = (rp + 8 * j) * 2;
        __half h0 = __float2half_rn(tile[oc][rr]);
        __half h1 = __float2half_rn(tile[oc][rr + 1]);
        size_t o = (size_t)(c0 + oc) * srcRows + r0 + rr;
        *(__half2*)(hT + o) = __halves2half2(h0, h1);
    }
}

// ===========================================================================
// HMMA GEMM, templated (XOR-swizzled smem, no padding):
//   NT=3: Out = (Ah+Al)*(Bh+Bl)^T  via  ah*bh + ah*bl + al*bh  (split-fp16)
//   NT=1: Out = Ah*Bh^T                                         (pure fp16)
//   STATS: epilogue also writes per-(row, 64-col warp tile) softmax partials
// Swizzle: BKH=32 -> SW64 (chunk ^= (row>>1)&3); BKH=64 -> SW128 (chunk ^= row&7)
// CTA 128x128, 8 warps (32x64), STAGES-deep cp.async pipeline, 2 CTAs/SM.
// ===========================================================================
template<int NT, int BKH, int STAGES, bool STATS>
__global__ __launch_bounds__(256, 2)
void gemm_hmma(const __half* __restrict__ Ah, const __half* __restrict__ Al,
               const __half* __restrict__ Bh, const __half* __restrict__ Bl,
               float* __restrict__ Out,
               int lda, int ldb, int ldc, int K,
               size_t aBatch, size_t bBatch, size_t cBatch) {
    constexpr int ROWB  = BKH * 2;             // bytes per smem row (64 or 128)
    constexpr int TILEB = 128 * ROWB;          // bytes per operand tile
    constexpr int NOP   = (NT == 3) ? 4 : 2;   // tiles per stage
    constexpr int STB   = NOP * TILEB;         // stage bytes
    constexpr int CPR   = BKH / 8;             // 16B chunks per row (4 or 8)
    constexpr int RST   = 256 / CPR;           // rows per loader pass
    constexpr int SWSH  = (BKH == 32) ? 1 : 0; // swizzle shift
    constexpr int SWMK  = CPR - 1;             // swizzle mask

    extern __shared__ char smem[];
    const uint32_t sb = smem_u32(smem);
    const int tid = threadIdx.x;
    const int lane = tid & 31;
    const int wid = tid >> 5;

    const int b = blockIdx.z;
    Ah += (size_t)b * aBatch;
    Bh += (size_t)b * bBatch;
    Out += (size_t)b * cBatch;
    if (NT == 3) { Al += (size_t)b * aBatch; Bl += (size_t)b * bBatch; }

    const int bm = blockIdx.y * BM;
    const int bn = blockIdx.x * BN;

    // ---- loader mapping (swizzled dst column is row-dependent but constant
    //      across the 64-row passes since RST is a multiple of 8) ----
    const int r0 = tid / CPR;
    const int ck0 = tid % CPR;
    const int chalves = ck0 * 8;                      // global k-offset (halves)
    const uint32_t swcol = (uint32_t)((ck0 ^ ((r0 >> SWSH) & SWMK)) * 16);
    const uint32_t sOffBase = (uint32_t)r0 * ROWB + swcol;

    const __half* pAh = Ah + (size_t)(bm + r0) * lda + chalves;
    const __half* pBh = Bh + (size_t)(bn + r0) * ldb + chalves;
    const __half* pAl = (NT == 3) ? Al + (size_t)(bm + r0) * lda + chalves : pAh;
    const __half* pBl = (NT == 3) ? Bl + (size_t)(bn + r0) * ldb + chalves : pBh;

    const int warpM = (wid & 3) * 32;
    const int warpN = (wid >> 2) * 64;

    float acc[2][8][4];
    #pragma unroll
    for (int i = 0; i < 2; i++)
        #pragma unroll
        for (int j = 0; j < 8; j++)
            #pragma unroll
            for (int k = 0; k < 4; k++) acc[i][j][k] = 0.0f;

    const int nIter = K / BKH;

    #define ISSUE_STAGE(st, ko) do {                                             \
        _Pragma("unroll")                                                        \
        for (int rr = 0; rr < 128; rr += RST) {                                  \
            const uint32_t so = sOffBase + (uint32_t)rr * ROWB;                  \
            cp16((st) + 0 * TILEB + so, pAh + (size_t)rr * lda + (ko));          \
            if (NT == 3) cp16((st) + 2 * TILEB + so, pAl + (size_t)rr * lda + (ko)); \
            cp16((st) + 1 * TILEB + so, pBh + (size_t)rr * ldb + (ko));          \
            if (NT == 3) cp16((st) + 3 * TILEB + so, pBl + (size_t)rr * ldb + (ko)); \
        }                                                                        \
        CP_COMMIT();                                                             \
    } while (0)

    // prologue: stages 0..STAGES-2
    #pragma unroll
    for (int i = 0; i < STAGES - 1; ++i)
        ISSUE_STAGE(sb + i * STB, (size_t)i * BKH);

    // ldmatrix lane pieces
    const int lr = lane & 15;
    const int lhi = (lane >> 4) & 1;
    const uint32_t lswz = (uint32_t)((lr >> SWSH) & SWMK);

    int cbuf = 0;                       // buffer of stage t
    int ibuf = (STAGES - 1) % STAGES;   // buffer to fill next

    for (int t = 0; t < nIter; ++t) {
        cp_wait<STAGES - 2>();  // with constant group-count invariant below,
        __syncthreads();        // this guarantees stage t resident

        if (t + STAGES - 1 < nIter) {
            ISSUE_STAGE(sb + ibuf * STB, (size_t)(t + STAGES - 1) * BKH);
        } else {
            CP_COMMIT();        // empty group keeps wait-count invariant (tail fix)
        }
        ibuf = (ibuf + 1 == STAGES) ? 0 : ibuf + 1;

        const uint32_t s0 = sb + cbuf * STB;
        cbuf = (cbuf + 1 == STAGES) ? 0 : cbuf + 1;

        #pragma unroll
        for (int kk = 0; kk < BKH / 16; ++kk) {
            const uint32_t cbyte = (uint32_t)(((kk * 2 + lhi) ^ lswz) << 4);
            uint32_t ah[2][4], al[2][4];
            #pragma unroll
            for (int mt = 0; mt < 2; ++mt) {
                const uint32_t aaddr = s0 + (uint32_t)(warpM + mt * 16 + lr) * ROWB + cbyte;
                LDMX4(ah[mt][0], ah[mt][1], ah[mt][2], ah[mt][3], aaddr);
                if (NT == 3)
                    LDMX4(al[mt][0], al[mt][1], al[mt][2], al[mt][3], aaddr + 2 * TILEB);
            }
            #pragma unroll
            for (int g = 0; g < 4; ++g) {
                const uint32_t baddr = s0 + (uint32_t)(warpN + g * 16 + lr) * ROWB
                                       + cbyte + 1 * TILEB;
                uint32_t bh0, bh1, bh2, bh3;
                LDMX4(bh0, bh1, bh2, bh3, baddr);
                if (NT == 3) {
                    uint32_t bl0, bl1, bl2, bl3;
                    LDMX4(bl0, bl1, bl2, bl3, baddr + 2 * TILEB);
                    #pragma unroll
                    for (int mt = 0; mt < 2; ++mt) {
                        MMA16816(acc[mt][2 * g],     ah[mt], bh0, bh2);
                        MMA16816(acc[mt][2 * g + 1], ah[mt], bh1, bh3);
                    }
                    #pragma unroll
                    for (int mt = 0; mt < 2; ++mt) {
                        MMA16816(acc[mt][2 * g],     ah[mt], bl0, bl2);
                        MMA16816(acc[mt][2 * g + 1], ah[mt], bl1, bl3);
                    }
                    #pragma unroll
                    for (int mt = 0; mt < 2; ++mt) {
                        MMA16816(acc[mt][2 * g],     al[mt], bh0, bh2);
                        MMA16816(acc[mt][2 * g + 1], al[mt], bh1, bh3);
                    }
                } else {
                    #pragma unroll
                    for (int mt = 0; mt < 2; ++mt) {
                        MMA16816(acc[mt][2 * g],     ah[mt], bh0, bh2);
                        MMA16816(acc[mt][2 * g + 1], ah[mt], bh1, bh3);
                    }
                }
            }
        }
    }
    #undef ISSUE_STAGE

    // ---- softmax partials: per-(row, 64-col warp tile) (max, sumexp) ----
    if (STATS) {
        #pragma unroll
        for (int mt = 0; mt < 2; ++mt) {
            float m0 = -3.4e38f, m1 = -3.4e38f;
            #pragma unroll
            for (int nf = 0; nf < 8; ++nf) {
                m0 = fmaxf(m0, fmaxf(acc[mt][nf][0], acc[mt][nf][1]));
                m1 = fmaxf(m1, fmaxf(acc[mt][nf][2], acc[mt][nf][3]));
            }
            m0 = fmaxf(m0, __shfl_xor_sync(0xFFFFFFFFu, m0, 1));
            m0 = fmaxf(m0, __shfl_xor_sync(0xFFFFFFFFu, m0, 2));
            m1 = fmaxf(m1, __shfl_xor_sync(0xFFFFFFFFu, m1, 1));
            m1 = fmaxf(m1, __shfl_xor_sync(0xFFFFFFFFu, m1, 2));
            float s0 = 0.0f, s1 = 0.0f;
            #pragma unroll
            for (int nf = 0; nf < 8; ++nf) {
                s0 += __expf(acc[mt][nf][0] - m0) + __expf(acc[mt][nf][1] - m0);
                s1 += __expf(acc[mt][nf][2] - m1) + __expf(acc[mt][nf][3] - m1);
            }
            s0 += __shfl_xor_sync(0xFFFFFFFFu, s0, 1);
            s0 += __shfl_xor_sync(0xFFFFFFFFu, s0, 2);
            s1 += __shfl_xor_sync(0xFFFFFFFFu, s1, 1);
            s1 += __shfl_xor_sync(0xFFFFFFFFu, s1, 2);
            if ((lane & 3) == 0) {
                const int row0 = bm + warpM + mt * 16 + (lane >> 2);
                const int pcol = (bn >> 6) + (warpN >> 6);
                g_part[(size_t)row0 * 64 + pcol]       = make_float2(m0, s0);
                g_part[(size_t)(row0 + 8) * 64 + pcol] = make_float2(m1, s1);
            }
        }
    }

    // ---- epilogue: direct fp32 stores (quad-contiguous 32B segments) ----
    #pragma unroll
    for (int mt = 0; mt < 2; ++mt) {
        #pragma unroll
        for (int nf = 0; nf < 8; ++nf) {
            const int row = bm + warpM + mt * 16 + (lane >> 2);
            const int col = bn + warpN + nf * 8 + (lane & 3) * 2;
            *(float2*)&Out[(size_t)row * ldc + col] =
                make_float2(acc[mt][nf][0], acc[mt][nf][1]);
            *(float2*)&Out[(size_t)(row + 8) * ldc + col] =
                make_float2(acc[mt][nf][2], acc[mt][nf][3]);
        }
    }
}

// ---------------------------------------------------------------------------
// Merge 64 per-tile partials per row -> per-row (max, 1/sum). One warp/row.
// ---------------------------------------------------------------------------
__global__ __launch_bounds__(256)
void merge_stats() {
    const int row = blockIdx.x * 8 + (threadIdx.x >> 5);
    const int lane = threadIdx.x & 31;
    float2 p0 = g_part[(size_t)row * 64 + lane];
    float2 p1 = g_part[(size_t)row * 64 + 32 + lane];
    float m = fmaxf(p0.x, p1.x);
    #pragma unroll
    for (int o = 16; o > 0; o >>= 1)
        m = fmaxf(m, __shfl_xor_sync(0xFFFFFFFFu, m, o));
    float s = p0.y * __expf(p0.x - m) + p1.y * __expf(p1.x - m);
    #pragma unroll
    for (int o = 16; o > 0; o >>= 1)
        s += __shfl_xor_sync(0xFFFFFFFFu, s, o);
    if (lane == 0) g_stats[row] = make_float2(m, 1.0f / s);
}

// ---------------------------------------------------------------------------
// Normalize scores -> probs (in place, fp32) AND write fp16 transposed A^T.
// ---------------------------------------------------------------------------
__global__ __launch_bounds__(256)
void norm_transpose(float* __restrict__ A, __half* __restrict__ AhT) {
    __shared__ float tile[32][65];
    __shared__ float2 st[64];
    const int b = blockIdx.z;
    float* Ab = A + (size_t)b * PS * PC;
    __half* hT = AhT + (size_t)b * PC * PS;
    const int c0 = blockIdx.x * 32;
    const int r0 = blockIdx.y * 64;
    const int t = threadIdx.x;
    if (t < 64) st[t] = g_stats[(size_t)b * PS + r0 + t];
    __syncthreads();
    const int lc = t & 31, lr = t >> 5;
    #pragma unroll
    for (int j = 0; j < 8; ++j) {
        const int row = lr + 8 * j;
        const size_t off = (size_t)(r0 + row) * PC + c0 + lc;
        const float2 s = st[row];
        const float p = __expf(Ab[off] - s.x) * s.y;
        tile[lc][row] = p;
        Ab[off] = p;
    }
    __syncthreads();
    const int oc = t >> 3, rp = t & 7;
    #pragma unroll
    for (int j = 0; j < 4; ++j) {
        const int rr = (rp + 8 * j) * 2;
        __half h0 = __float2half_rn(tile[oc][rr]);
        __half h1 = __float2half_rn(tile[oc][rr + 1]);
        const size_t o = (size_t)(c0 + oc) * PS + r0 + rr;
        *(__half2*)(hT + o) = __halves2half2(h0, h1);
    }
}

// ===========================================================================
// Launch.  d_out layout: [output (B*C*D floats) | A (B*S*C floats)]
// ===========================================================================
extern "C" void kernel_launch(void* const* d_in, const int* in_sizes, int n_in,
                              void* d_out, int out_size) {
    const float* x = (const float*)d_in[0];    // [B,S,D]
    const float* lab = (const float*)d_in[1];  // [C,D]
    float* out = (float*)d_out;
    float* Aout = out + (size_t)PB * PC * PD;  // [B*S, C]

    void *pXh, *pXl, *pLh, *pLl, *pXhT, *pAhT;
    cudaGetSymbolAddress(&pXh, g_Xh);   cudaGetSymbolAddress(&pXl, g_Xl);
    cudaGetSymbolAddress(&pLh, g_Lh);   cudaGetSymbolAddress(&pLl, g_Ll);
    cudaGetSymbolAddress(&pXhT, g_XhT); cudaGetSymbolAddress(&pAhT, g_AhT);

    // GEMM1: NT=3, BK=32, 3 stages, swizzled -> 3*4*8192  = 98304 B (2 CTAs/SM)
    const int SMEM_G1 = 3 * 4 * 128 * 64;
    // GEMM2: NT=1, BK=64, 3 stages, swizzled -> 3*2*16384 = 98304 B (2 CTAs/SM)
    const int SMEM_G2 = 3 * 2 * 128 * 128;
    cudaFuncSetAttribute((const void*)gemm_hmma<3, 32, 3, true>,
                         cudaFuncAttributeMaxDynamicSharedMemorySize, SMEM_G1);
    cudaFuncSetAttribute((const void*)gemm_hmma<1, 64, 3, false>,
                         cudaFuncAttributeMaxDynamicSharedMemorySize, SMEM_G2);

    // 1. fp16 splits of X and L
    split_kernel<<<(PB * PS * PD / 4 + 255) / 256, 256>>>(
        x, (__half*)pXh, (__half*)pXl, PB * PS * PD / 4);
    split_kernel<<<(PC * PD / 4 + 255) / 256, 256>>>(
        lab, (__half*)pLh, (__half*)pLl, PC * PD / 4);

    // 2. X^T (hi only) per batch: [S,D] -> [D,S]
    {
        dim3 g(PD / 32, PS / 64, PB);
        transpose_h<<<g, 256>>>(x, (__half*)pXhT, PS, PD,
                                (size_t)PS * PD, (size_t)PD * PS);
    }

    // 3. GEMM1 (split-fp16, 3 terms + softmax partials): scores[B*S, C] = X @ L^T
    {
        dim3 g(PC / BN, (PB * PS) / BM, 1);
        gemm_hmma<3, 32, 3, true><<<g, 256, SMEM_G1>>>(
            (const __half*)pXh, (const __half*)pXl,
            (const __half*)pLh, (const __half*)pLl,
            Aout, PD, PD, PC, PD, 0, 0, 0);
    }

    // 4. merge row partials -> (max, 1/sum)
    merge_stats<<<PB * PS / 8, 256>>>();

    // 5. normalize scores in place + write fp16 A^T
    {
        dim3 g(PC / 32, PS / 64, PB);
        norm_transpose<<<g, 256>>>(Aout, (__half*)pAhT);
    }

    // 6. GEMM2 (pure fp16): out[C, D] = A^T @ X   per batch
    {
        dim3 g(PD / BN, PC / BM, PB);
        gemm_hmma<1, 64, 3, false><<<g, 256, SMEM_G2>>>(
            (const __half*)pAhT, (const __half*)pAhT,
            (const __half*)pXhT, (const __half*)pXhT,
            out, PS, PS, PD, PS,
            (size_t)PC * PS, (size_t)PD * PS, (size_t)PC * PD);
    }
}